// round 14
// baseline (speedup 1.0000x reference)
#include <cuda_runtime.h>
#include <cuda_fp16.h>
#include <cstdint>
#include <math.h>

#define BB   2
#define NN   2000
#define KK   32
#define HH   128
#define EPSC 1e-6f

// ---------------- device scratch (__device__ globals, no alloc) -------------
__device__ uint2 g_WQf[16 * 8 * 32];
__device__ uint2 g_W1f[16 * 8 * 32];
__device__ uint2 g_W2f[16 * 8 * 32];
// Fused value matrix Mfull[1024 x 128] fp16 fragments (Mfull = W_V(head) x W_O)
__device__ uint2 g_Mf[16 * 64 * 32];
__device__ __half g_Qh [4000 * 128];
__device__ float  g_att[4000 * 128];
__device__ __half g_Y  [4000 * 1024];

__device__ __forceinline__ unsigned int h2u(__half2 h) {
    return *(unsigned int*)&h;
}
__device__ __forceinline__ void cp_async16(void* dst_smem, const void* src) {
    unsigned int d = (unsigned int)__cvta_generic_to_shared(dst_smem);
    asm volatile("cp.async.cg.shared.global [%0], [%1], 16;" :: "r"(d), "l"(src));
}
__device__ __forceinline__ void cp_async_commit() {
    asm volatile("cp.async.commit_group;");
}
__device__ __forceinline__ void cp_async_wait0() {
    asm volatile("cp.async.wait_group 0;");
}

// ---------------- pack: weight fragments + Mfull ----------------------------
__global__ void pack_kernel(const float* __restrict__ WQ,
                            const float* __restrict__ WK1,
                            const float* __restrict__ WK2,
                            const float* __restrict__ WV,
                            const float* __restrict__ WO) {
    __shared__ float sWO[128 * 33];
    __shared__ float sWV[32 * 32];
    if (blockIdx.x < 16) {
        int t = blockIdx.x * 256 + threadIdx.x;   // 0..4095
        int lane = t & 31;
        int ks   = (t >> 5) & 7;
        int nt8  = t >> 8;
        int g    = lane >> 2;
        int tid4 = lane & 3;
        int n    = nt8 * 8 + g;
        int k0   = ks * 16 + tid4 * 2;
        uint2 uq, u1, u2;
        uq.x = h2u(__floats2half2_rn(WQ [n * 128 + k0],     WQ [n * 128 + k0 + 1]));
        uq.y = h2u(__floats2half2_rn(WQ [n * 128 + k0 + 8], WQ [n * 128 + k0 + 9]));
        u1.x = h2u(__floats2half2_rn(WK1[n * 128 + k0],     WK1[n * 128 + k0 + 1]));
        u1.y = h2u(__floats2half2_rn(WK1[n * 128 + k0 + 8], WK1[n * 128 + k0 + 9]));
        u2.x = h2u(__floats2half2_rn(WK2[n * 128 + k0],     WK2[n * 128 + k0 + 1]));
        u2.y = h2u(__floats2half2_rn(WK2[n * 128 + k0 + 8], WK2[n * 128 + k0 + 9]));
        g_WQf[t] = uq; g_W1f[t] = u1; g_W2f[t] = u2;
    } else {
        int bid = blockIdx.x - 16;        // 0..31
        int h   = bid >> 3;               // head
        int jc  = bid & 7;                // 32-wide j chunk within head
        int tid = threadIdx.x;
        for (int i = tid; i < 128 * 32; i += 256) {
            int o = i >> 5, ii = i & 31;
            sWO[o * 33 + ii] = WO[o * 128 + h * 32 + ii];
        }
        for (int i = tid; i < 32 * 32; i += 256) {
            int ii = i >> 5, jj = i & 31;
            sWV[ii * 32 + jj] = WV[(h * 32 + ii) * 256 + jc * 32 + jj];
        }
        __syncthreads();
        int o    = tid & 127;
        int jsel = tid >> 7;
        float wo[32];
#pragma unroll
        for (int ii = 0; ii < 32; ++ii) wo[ii] = sWO[o * 33 + ii];
        float m[16];
#pragma unroll
        for (int jj2 = 0; jj2 < 16; ++jj2) {
            int jj = jsel * 16 + jj2;
            float a = 0.f;
#pragma unroll
            for (int ii = 0; ii < 32; ++ii) a += sWV[ii * 32 + jj] * wo[ii];
            m[jj2] = a;
        }
        int ks = h * 16 + jc * 2 + jsel;
        int nt = o >> 3;
        int g  = o & 7;
#pragma unroll
        for (int tid4 = 0; tid4 < 4; ++tid4) {
            int k0l = tid4 * 2;
            uint2 u;
            u.x = h2u(__floats2half2_rn(m[k0l],     m[k0l + 1]));
            u.y = h2u(__floats2half2_rn(m[k0l + 8], m[k0l + 9]));
            g_Mf[(nt * 64 + ks) * 32 + (g << 2 | tid4)] = u;
        }
    }
}

// ---------------- PTX helpers ----------------
__device__ __forceinline__ void ldsm_x4(unsigned int* r, const void* p) {
    unsigned int a = (unsigned int)__cvta_generic_to_shared(p);
    asm volatile("ldmatrix.sync.aligned.m8n8.x4.shared.b16 {%0,%1,%2,%3}, [%4];"
                 : "=r"(r[0]), "=r"(r[1]), "=r"(r[2]), "=r"(r[3]) : "r"(a));
}
__device__ __forceinline__ void mma16816(float* d, const unsigned int* a,
                                         unsigned int b0, unsigned int b1) {
    asm volatile("mma.sync.aligned.m16n8k16.row.col.f32.f16.f16.f32 "
                 "{%0,%1,%2,%3}, {%4,%5,%6,%7}, {%8,%9}, {%0,%1,%2,%3};"
                 : "+f"(d[0]), "+f"(d[1]), "+f"(d[2]), "+f"(d[3])
                 : "r"(a[0]), "r"(a[1]), "r"(a[2]), "r"(a[3]), "r"(b0), "r"(b1));
}

// ---------------- qgemm: Q = h_V @ W_Q^T -> g_Qh (fp16 mma) -----------------
__global__ void __launch_bounds__(128)
qgemm_kernel(const float* __restrict__ h_V) {
    __shared__ __half sA[32 * 136];
    const int t    = threadIdx.x;
    const int w    = t >> 5;
    const int lane = t & 31;
    const int g    = lane >> 2;
    const int tid4 = lane & 3;
    const int node0 = blockIdx.x * 32;

    const float4* hv4 = (const float4*)h_V;
#pragma unroll
    for (int it = 0; it < 8; ++it) {
        int f4 = it * 128 + t;
        int r  = f4 >> 5, c4 = f4 & 31;
        float4 v = hv4[(size_t)(node0 + r) * 32 + c4];
        __half2* p = (__half2*)(sA + r * 136 + c4 * 4);
        p[0] = __floats2half2_rn(v.x, v.y);
        p[1] = __floats2half2_rn(v.z, v.w);
    }
    __syncthreads();

    float acc[2][4][4];
#pragma unroll
    for (int m = 0; m < 2; ++m)
#pragma unroll
        for (int n = 0; n < 4; ++n)
#pragma unroll
            for (int c = 0; c < 4; ++c) acc[m][n][c] = 0.f;

    const int arow = lane & 15, acol8 = (lane >> 4) * 8;
#pragma unroll
    for (int ks = 0; ks < 8; ++ks) {
        unsigned int a[2][4];
#pragma unroll
        for (int m = 0; m < 2; ++m)
            ldsm_x4(a[m], sA + (m * 16 + arow) * 136 + ks * 16 + acol8);
#pragma unroll
        for (int n = 0; n < 4; ++n) {
            uint2 b = g_WQf[(((w * 4 + n) * 8 + ks) * 32) + lane];
            mma16816(acc[0][n], a[0], b.x, b.y);
            mma16816(acc[1][n], a[1], b.x, b.y);
        }
    }
#pragma unroll
    for (int m = 0; m < 2; ++m)
#pragma unroll
        for (int n = 0; n < 4; ++n) {
            int col = w * 32 + n * 8 + tid4 * 2;
            int r0  = node0 + m * 16 + g;
            *(__half2*)&g_Qh[(size_t)r0 * 128 + col] =
                __floats2half2_rn(acc[m][n][0], acc[m][n][1]);
            *(__half2*)&g_Qh[(size_t)(r0 + 8) * 128 + col] =
                __floats2half2_rn(acc[m][n][2], acc[m][n][3]);
        }
}

// ---------------- attn1: logits + softmax -> g_att ---------------------------
// 256 threads, 8 warps: warp = (head h = w>>1, m-half mh = w&1). 32-reg acc.
#define KROW 136
__global__ void __launch_bounds__(256, 3)
attn1_kernel(const float* __restrict__ h_KV,
             const float* __restrict__ h_KE,
             const float* __restrict__ mask_attend) {
    extern __shared__ float smbuf[];
    float*  s_q      = smbuf;                     // 128
    float*  s_logits = s_q + 128;                 // 128
    __half* s_keh    = (__half*)(s_logits + 128); // 32*KROW
    __half* s_kvh    = s_keh + 32 * KROW;         // 32*KROW

    const int bn   = blockIdx.x;
    const int t    = threadIdx.x;
    const int w    = t >> 5;
    const int lane = t & 31;
    const int g    = lane >> 2;
    const int tid4 = lane & 3;
    const int h    = w >> 1;      // head
    const int mh   = w & 1;       // m-half (neighbors [mh*16, mh*16+16))

    const float mk = mask_attend[(size_t)bn * KK + lane];

    // stage KE/KV as fp16 (256 threads -> 4 iters)
    {
        const float4* gke = (const float4*)(h_KE + (size_t)bn * KK * 128);
        const float4* gkv = (const float4*)(h_KV + (size_t)bn * KK * 128);
#pragma unroll
        for (int r = 0; r < 4; ++r) {
            int e4 = r * 256 + t;             // 0..1023
            int k  = e4 >> 5;
            int j  = (e4 & 31) * 4;
            float4 a = gke[e4];
            float4 b = gkv[e4];
            uint2 ua, ub;
            ua.x = h2u(__floats2half2_rn(a.x, a.y));
            ua.y = h2u(__floats2half2_rn(a.z, a.w));
            ub.x = h2u(__floats2half2_rn(b.x, b.y));
            ub.y = h2u(__floats2half2_rn(b.z, b.w));
            *(uint2*)(s_keh + k * KROW + j) = ua;
            *(uint2*)(s_kvh + k * KROW + j) = ub;
        }
        if (t < 128) s_q[t] = __half2float(g_Qh[(size_t)bn * 128 + t]);
    }
    __syncthreads();

    // K1/K2 mma: warp computes 16(k) x 32(d) tile of K1 and K2 for head h.
    float acc1[4][4], acc2[4][4];
#pragma unroll
    for (int n = 0; n < 4; ++n)
#pragma unroll
        for (int c = 0; c < 4; ++c) { acc1[n][c] = 0.f; acc2[n][c] = 0.f; }

    const int arow = lane & 15, acol8 = (lane >> 4) * 8;
#pragma unroll
    for (int ks = 0; ks < 8; ++ks) {
        unsigned int a1[4], a2[4];
        ldsm_x4(a1, s_keh + (mh * 16 + arow) * KROW + ks * 16 + acol8);
        ldsm_x4(a2, s_kvh + (mh * 16 + arow) * KROW + ks * 16 + acol8);
#pragma unroll
        for (int n = 0; n < 4; ++n) {
            int f = (((h * 4 + n) * 8 + ks) * 32) + lane;
            uint2 b1 = g_W1f[f];
            uint2 b2 = g_W2f[f];
            mma16816(acc1[n], a1, b1.x, b1.y);
            mma16816(acc2[n], a2, b2.x, b2.y);
        }
    }

    // logits[h][k] = (1/32) sum_d q*K1*K2  (rows g -> k=mh*16+g, g+8)
    {
        float p0 = 0.f, p1 = 0.f;
#pragma unroll
        for (int n = 0; n < 4; ++n) {
            int j0 = h * 32 + n * 8 + tid4 * 2;
            float q0 = s_q[j0], q1 = s_q[j0 + 1];
            p0 += q0 * acc1[n][0] * acc2[n][0] + q1 * acc1[n][1] * acc2[n][1];
            p1 += q0 * acc1[n][2] * acc2[n][2] + q1 * acc1[n][3] * acc2[n][3];
        }
        p0 += __shfl_xor_sync(0xffffffffu, p0, 1);
        p0 += __shfl_xor_sync(0xffffffffu, p0, 2);
        p1 += __shfl_xor_sync(0xffffffffu, p1, 1);
        p1 += __shfl_xor_sync(0xffffffffu, p1, 2);
        if (tid4 == 0) {
            s_logits[h * 32 + mh * 16 + g]     = p0 * (1.0f / 32.0f);
            s_logits[h * 32 + mh * 16 + g + 8] = p1 * (1.0f / 32.0f);
        }
    }
    __syncthreads();

    // masked softmax: warps 0..3 = heads, lane = neighbor k -> g_att
    if (w < 4) {
        float l = s_logits[w * 32 + lane];
        l = (mk > 0.f) ? l : -3.402823466e38f;
        float mx = l;
#pragma unroll
        for (int off = 16; off > 0; off >>= 1)
            mx = fmaxf(mx, __shfl_xor_sync(0xffffffffu, mx, off));
        float e = expf(l - mx);
        float s = e;
#pragma unroll
        for (int off = 16; off > 0; off >>= 1)
            s += __shfl_xor_sync(0xffffffffu, s, off);
        g_att[(size_t)bn * 128 + w * 32 + lane] = mk * e / s;
    }
}

// ---------------- attn2: Y = att^T @ EV (pure streaming) --------------------
// grid 4000 x 256; thread t owns column t for all 4 heads.
__global__ void __launch_bounds__(256)
attn2_kernel(const float* __restrict__ h_EV) {
    __shared__ float s_att[128];
    const int bn = blockIdx.x;
    const int t  = threadIdx.x;

    if (t < 128) s_att[t] = g_att[(size_t)bn * 128 + t];
    __syncthreads();

    const float* ev = h_EV + (size_t)bn * KK * 256 + t;
    float a0 = 0.f, a1 = 0.f, a2 = 0.f, a3 = 0.f;
#pragma unroll 8
    for (int k = 0; k < 32; ++k) {
        float e  = ev[k * 256];
        a0 += s_att[k]      * e;
        a1 += s_att[32 + k] * e;
        a2 += s_att[64 + k] * e;
        a3 += s_att[96 + k] * e;
    }
    __half* gy = g_Y + (size_t)bn * 1024 + t;
    gy[0]   = __float2half_rn(a0);
    gy[256] = __float2half_rn(a1);
    gy[512] = __float2half_rn(a2);
    gy[768] = __float2half_rn(a3);
}

// ---------------- out: out = LN(h_V + Y @ Mfull) (R9 proven) ----------------
__global__ void __launch_bounds__(256)
out_kernel(const float* __restrict__ h_V,
           const float* __restrict__ mask_V,
           const float* __restrict__ gain,
           const float* __restrict__ bias,
           float* __restrict__ out) {
    extern __shared__ float smf[];
    float*  sRed = smf;                        // 2 * 32 * 132 floats
    __half* sY   = (__half*)(sRed + 2 * 32 * 132);  // 32 * 1032 halves

    const int t    = threadIdx.x;
    const int w    = t >> 5;
    const int lane = t & 31;
    const int g    = lane >> 2;
    const int tid4 = lane & 3;
    const int node0 = blockIdx.x * 32;
    const int nt4  = w & 3;                    // 32-col tile
    const int kh   = w >> 2;                   // K half

    {
#pragma unroll
        for (int it = 0; it < 16; ++it) {
            int f = it * 256 + t;              // 0..4095 (16B chunks)
            int r = f >> 7, c = f & 127;
            cp_async16(sY + r * 1032 + c * 8,
                       g_Y + (size_t)(node0 + r) * 1024 + c * 8);
        }
        cp_async_commit();
        cp_async_wait0();
    }
    __syncthreads();

    float acc[2][4][4];
#pragma unroll
    for (int m = 0; m < 2; ++m)
#pragma unroll
        for (int n = 0; n < 4; ++n)
#pragma unroll
            for (int c = 0; c < 4; ++c) acc[m][n][c] = 0.f;

    const int arow = lane & 15, acol8 = (lane >> 4) * 8;
    const int ks0  = kh * 32;

    unsigned int aA[2][4], aB[2][4];
    uint2 bA[4], bB[4];
#pragma unroll
    for (int m = 0; m < 2; ++m)
        ldsm_x4(aA[m], sY + (m * 16 + arow) * 1032 + ks0 * 16 + acol8);
#pragma unroll
    for (int n = 0; n < 4; ++n)
        bA[n] = g_Mf[(((nt4 * 4 + n) * 64 + ks0) * 32) + lane];

#pragma unroll
    for (int ksl = 0; ksl < 32; ++ksl) {
        unsigned int (*ac)[4] = (ksl & 1) ? aB : aA;
        unsigned int (*an)[4] = (ksl & 1) ? aA : aB;
        uint2* bc = (ksl & 1) ? bB : bA;
        uint2* bn = (ksl & 1) ? bA : bB;
        if (ksl < 31) {
            int ks = ks0 + ksl + 1;
#pragma unroll
            for (int m = 0; m < 2; ++m)
                ldsm_x4(an[m], sY + (m * 16 + arow) * 1032 + ks * 16 + acol8);
#pragma unroll
            for (int n = 0; n < 4; ++n)
                bn[n] = g_Mf[(((nt4 * 4 + n) * 64 + ks) * 32) + lane];
        }
#pragma unroll
        for (int n = 0; n < 4; ++n) {
            mma16816(acc[0][n], ac[0], bc[n].x, bc[n].y);
            mma16816(acc[1][n], ac[1], bc[n].x, bc[n].y);
        }
    }

#pragma unroll
    for (int m = 0; m < 2; ++m)
#pragma unroll
        for (int n = 0; n < 4; ++n) {
            int col = (nt4 * 4 + n) * 8 + tid4 * 2;
            int r0  = m * 16 + g;
            float* base = sRed + kh * 32 * 132;
            base[r0 * 132 + col]           = acc[m][n][0];
            base[r0 * 132 + col + 1]       = acc[m][n][1];
            base[(r0 + 8) * 132 + col]     = acc[m][n][2];
            base[(r0 + 8) * 132 + col + 1] = acc[m][n][3];
        }
    __syncthreads();

    {
        const float4* hv4 = (const float4*)h_V;
        const float4 gg = ((const float4*)gain)[lane];
        const float4 bb = ((const float4*)bias)[lane];
#pragma unroll
        for (int rr = 0; rr < 4; ++rr) {
            int r    = w * 4 + rr;
            int node = node0 + r;
            float4 c0 = *(float4*)&sRed[r * 132 + lane * 4];
            float4 c1 = *(float4*)&sRed[32 * 132 + r * 132 + lane * 4];
            float4 hv = hv4[(size_t)node * 32 + lane];
            float4 x;
            x.x = c0.x + c1.x + hv.x;
            x.y = c0.y + c1.y + hv.y;
            x.z = c0.z + c1.z + hv.z;
            x.w = c0.w + c1.w + hv.w;
            float sum = x.x + x.y + x.z + x.w;
            float sq  = x.x * x.x + x.y * x.y + x.z * x.z + x.w * x.w;
#pragma unroll
            for (int off = 16; off > 0; off >>= 1) {
                sum += __shfl_xor_sync(0xffffffffu, sum, off);
                sq  += __shfl_xor_sync(0xffffffffu, sq, off);
            }
            float mu  = sum * (1.f / 128.f);
            float var = (sq - sum * mu) * (1.f / 127.f);
            float sig = sqrtf(var + EPSC);
            float mk  = mask_V[node];
            float iv  = mk / (sig + EPSC);
            float4 o;
            o.x = (x.x - mu) * iv * gg.x + mk * bb.x;
            o.y = (x.y - mu) * iv * gg.y + mk * bb.y;
            o.z = (x.z - mu) * iv * gg.z + mk * bb.z;
            o.w = (x.w - mu) * iv * gg.w + mk * bb.w;
            ((float4*)out)[(size_t)node * 32 + lane] = o;
        }
    }
}

static const int ATTN1_SMEM = (128 + 128) * 4 + 2 * 32 * KROW * 2;
static const int OUT_SMEM   = (2 * 32 * 132) * 4 + 32 * 1032 * 2;

extern "C" void kernel_launch(void* const* d_in, const int* in_sizes, int n_in,
                              void* d_out, int out_size) {
    const float* h_V         = (const float*)d_in[0];
    const float* h_EV        = (const float*)d_in[1];
    const float* h_KV        = (const float*)d_in[2];
    const float* h_KE        = (const float*)d_in[3];
    const float* mask_V      = (const float*)d_in[4];
    const float* mask_attend = (const float*)d_in[5];
    const float* W_Q         = (const float*)d_in[6];
    const float* W_K1        = (const float*)d_in[7];
    const float* W_K2        = (const float*)d_in[8];
    const float* W_V         = (const float*)d_in[9];
    const float* W_O         = (const float*)d_in[10];
    const float* gain        = (const float*)d_in[11];
    const float* bias        = (const float*)d_in[12];
    float* out = (float*)d_out;

    pack_kernel<<<48, 256>>>(W_Q, W_K1, W_K2, W_V, W_O);
    qgemm_kernel<<<125, 128>>>(h_V);

    cudaFuncSetAttribute(attn1_kernel,
                         cudaFuncAttributeMaxDynamicSharedMemorySize, ATTN1_SMEM);
    attn1_kernel<<<BB * NN, 256, ATTN1_SMEM>>>(h_KV, h_KE, mask_attend);

    attn2_kernel<<<BB * NN, 256>>>(h_EV);

    cudaFuncSetAttribute(out_kernel,
                         cudaFuncAttributeMaxDynamicSharedMemorySize, OUT_SMEM);
    out_kernel<<<125, 256, OUT_SMEM>>>(h_V, mask_V, gain, bias, out);
}

// round 15
// speedup vs baseline: 1.3031x; 1.3031x over previous
#include <cuda_runtime.h>
#include <cuda_fp16.h>
#include <cstdint>
#include <math.h>

#define BB   2
#define NN   2000
#define KK   32
#define HH   128
#define EPSC 1e-6f

// ---------------- device scratch (__device__ globals, no alloc) -------------
__device__ uint2 g_WQf[16 * 8 * 32];
__device__ uint2 g_W1f[16 * 8 * 32];
__device__ uint2 g_W2f[16 * 8 * 32];
// Fused value matrix Mfull[1024 x 128] fp16 fragments (Mfull = W_V(head) x W_O)
__device__ uint2 g_Mf[16 * 64 * 32];
__device__ __half g_Qh[4000 * 128];
__device__ __half g_Y [4000 * 1024];

__device__ __forceinline__ unsigned int h2u(__half2 h) {
    return *(unsigned int*)&h;
}
__device__ __forceinline__ void cp_async16(void* dst_smem, const void* src) {
    unsigned int d = (unsigned int)__cvta_generic_to_shared(dst_smem);
    asm volatile("cp.async.cg.shared.global [%0], [%1], 16;" :: "r"(d), "l"(src));
}
__device__ __forceinline__ void cp_async_commit() {
    asm volatile("cp.async.commit_group;");
}
__device__ __forceinline__ void cp_async_wait0() {
    asm volatile("cp.async.wait_group 0;");
}
__device__ __forceinline__ void cp_async_wait1() {
    asm volatile("cp.async.wait_group 1;");
}
__device__ __forceinline__ void cp_async_wait2() {
    asm volatile("cp.async.wait_group 2;");
}

// ---------------- pack: weight fragments + Mfull ----------------------------
__global__ void pack_kernel(const float* __restrict__ WQ,
                            const float* __restrict__ WK1,
                            const float* __restrict__ WK2,
                            const float* __restrict__ WV,
                            const float* __restrict__ WO) {
    __shared__ float sWO[128 * 33];
    __shared__ float sWV[32 * 32];
    if (blockIdx.x < 16) {
        int t = blockIdx.x * 256 + threadIdx.x;   // 0..4095
        int lane = t & 31;
        int ks   = (t >> 5) & 7;
        int nt8  = t >> 8;
        int g    = lane >> 2;
        int tid4 = lane & 3;
        int n    = nt8 * 8 + g;
        int k0   = ks * 16 + tid4 * 2;
        uint2 uq, u1, u2;
        uq.x = h2u(__floats2half2_rn(WQ [n * 128 + k0],     WQ [n * 128 + k0 + 1]));
        uq.y = h2u(__floats2half2_rn(WQ [n * 128 + k0 + 8], WQ [n * 128 + k0 + 9]));
        u1.x = h2u(__floats2half2_rn(WK1[n * 128 + k0],     WK1[n * 128 + k0 + 1]));
        u1.y = h2u(__floats2half2_rn(WK1[n * 128 + k0 + 8], WK1[n * 128 + k0 + 9]));
        u2.x = h2u(__floats2half2_rn(WK2[n * 128 + k0],     WK2[n * 128 + k0 + 1]));
        u2.y = h2u(__floats2half2_rn(WK2[n * 128 + k0 + 8], WK2[n * 128 + k0 + 9]));
        g_WQf[t] = uq; g_W1f[t] = u1; g_W2f[t] = u2;
    } else {
        int bid = blockIdx.x - 16;        // 0..31
        int h   = bid >> 3;               // head
        int jc  = bid & 7;                // 32-wide j chunk within head
        int tid = threadIdx.x;
        for (int i = tid; i < 128 * 32; i += 256) {
            int o = i >> 5, ii = i & 31;
            sWO[o * 33 + ii] = WO[o * 128 + h * 32 + ii];
        }
        for (int i = tid; i < 32 * 32; i += 256) {
            int ii = i >> 5, jj = i & 31;
            sWV[ii * 32 + jj] = WV[(h * 32 + ii) * 256 + jc * 32 + jj];
        }
        __syncthreads();
        int o    = tid & 127;
        int jsel = tid >> 7;
        float wo[32];
#pragma unroll
        for (int ii = 0; ii < 32; ++ii) wo[ii] = sWO[o * 33 + ii];
        float m[16];
#pragma unroll
        for (int jj2 = 0; jj2 < 16; ++jj2) {
            int jj = jsel * 16 + jj2;
            float a = 0.f;
#pragma unroll
            for (int ii = 0; ii < 32; ++ii) a += sWV[ii * 32 + jj] * wo[ii];
            m[jj2] = a;
        }
        int ks = h * 16 + jc * 2 + jsel;
        int nt = o >> 3;
        int g  = o & 7;
#pragma unroll
        for (int tid4 = 0; tid4 < 4; ++tid4) {
            int k0l = tid4 * 2;
            uint2 u;
            u.x = h2u(__floats2half2_rn(m[k0l],     m[k0l + 1]));
            u.y = h2u(__floats2half2_rn(m[k0l + 8], m[k0l + 9]));
            g_Mf[(nt * 64 + ks) * 32 + (g << 2 | tid4)] = u;
        }
    }
}

// ---------------- PTX helpers ----------------
__device__ __forceinline__ void ldsm_x4(unsigned int* r, const void* p) {
    unsigned int a = (unsigned int)__cvta_generic_to_shared(p);
    asm volatile("ldmatrix.sync.aligned.m8n8.x4.shared.b16 {%0,%1,%2,%3}, [%4];"
                 : "=r"(r[0]), "=r"(r[1]), "=r"(r[2]), "=r"(r[3]) : "r"(a));
}
__device__ __forceinline__ void mma16816(float* d, const unsigned int* a,
                                         unsigned int b0, unsigned int b1) {
    asm volatile("mma.sync.aligned.m16n8k16.row.col.f32.f16.f16.f32 "
                 "{%0,%1,%2,%3}, {%4,%5,%6,%7}, {%8,%9}, {%0,%1,%2,%3};"
                 : "+f"(d[0]), "+f"(d[1]), "+f"(d[2]), "+f"(d[3])
                 : "r"(a[0]), "r"(a[1]), "r"(a[2]), "r"(a[3]), "r"(b0), "r"(b1));
}

// ---------------- qgemm: Q = h_V @ W_Q^T -> g_Qh (fp16 mma) -----------------
__global__ void __launch_bounds__(128)
qgemm_kernel(const float* __restrict__ h_V) {
    __shared__ __half sA[32 * 136];
    const int t    = threadIdx.x;
    const int w    = t >> 5;
    const int lane = t & 31;
    const int g    = lane >> 2;
    const int tid4 = lane & 3;
    const int node0 = blockIdx.x * 32;

    const float4* hv4 = (const float4*)h_V;
#pragma unroll
    for (int it = 0; it < 8; ++it) {
        int f4 = it * 128 + t;
        int r  = f4 >> 5, c4 = f4 & 31;
        float4 v = hv4[(size_t)(node0 + r) * 32 + c4];
        __half2* p = (__half2*)(sA + r * 136 + c4 * 4);
        p[0] = __floats2half2_rn(v.x, v.y);
        p[1] = __floats2half2_rn(v.z, v.w);
    }
    __syncthreads();

    float acc[2][4][4];
#pragma unroll
    for (int m = 0; m < 2; ++m)
#pragma unroll
        for (int n = 0; n < 4; ++n)
#pragma unroll
            for (int c = 0; c < 4; ++c) acc[m][n][c] = 0.f;

    const int arow = lane & 15, acol8 = (lane >> 4) * 8;
#pragma unroll
    for (int ks = 0; ks < 8; ++ks) {
        unsigned int a[2][4];
#pragma unroll
        for (int m = 0; m < 2; ++m)
            ldsm_x4(a[m], sA + (m * 16 + arow) * 136 + ks * 16 + acol8);
#pragma unroll
        for (int n = 0; n < 4; ++n) {
            uint2 b = g_WQf[(((w * 4 + n) * 8 + ks) * 32) + lane];
            mma16816(acc[0][n], a[0], b.x, b.y);
            mma16816(acc[1][n], a[1], b.x, b.y);
        }
    }
#pragma unroll
    for (int m = 0; m < 2; ++m)
#pragma unroll
        for (int n = 0; n < 4; ++n) {
            int col = w * 32 + n * 8 + tid4 * 2;
            int r0  = node0 + m * 16 + g;
            *(__half2*)&g_Qh[(size_t)r0 * 128 + col] =
                __floats2half2_rn(acc[m][n][0], acc[m][n][1]);
            *(__half2*)&g_Qh[(size_t)(r0 + 8) * 128 + col] =
                __floats2half2_rn(acc[m][n][2], acc[m][n][3]);
        }
}

// ---------------- attn: per node -> Y (R12 proven best) ----------------------
#define KROW 136
__global__ void __launch_bounds__(128, 4)
attn_kernel(const float* __restrict__ h_EV,
            const float* __restrict__ h_KV,
            const float* __restrict__ h_KE,
            const float* __restrict__ mask_attend) {
    extern __shared__ float smbuf[];
    float*  s_q      = smbuf;                    // 128
    float*  s_logits = s_q + 128;                // 128
    float*  s_att    = s_logits + 128;           // 128
    float*  s_ev     = s_att + 128;              // 32*256 = 8192
    __half* s_keh    = (__half*)(s_ev + 8192);   // 32*KROW
    __half* s_kvh    = s_keh + 32 * KROW;        // 32*KROW

    const int bn   = blockIdx.x;
    const int t    = threadIdx.x;
    const int w    = t >> 5;
    const int lane = t & 31;
    const int g    = lane >> 2;
    const int tid4 = lane & 3;

    const float mk = mask_attend[(size_t)bn * KK + lane];

    // prefetch EV (fp32) via cp.async — overlaps the whole mma phase
    {
        const float4* gev = (const float4*)(h_EV + (size_t)bn * KK * 256);
#pragma unroll
        for (int it = 0; it < 16; ++it) {
            int idx = it * 128 + t;              // 0..2047 float4s
            cp_async16(s_ev + idx * 4, gev + idx);
        }
        cp_async_commit();
    }

    // stage KE/KV as fp16
    {
        const float4* gke = (const float4*)(h_KE + (size_t)bn * KK * 128);
        const float4* gkv = (const float4*)(h_KV + (size_t)bn * KK * 128);
#pragma unroll
        for (int r = 0; r < 8; ++r) {
            int e4 = r * 128 + t;
            int k  = e4 >> 5;
            int j  = (e4 & 31) * 4;
            float4 a = gke[e4];
            float4 b = gkv[e4];
            uint2 ua, ub;
            ua.x = h2u(__floats2half2_rn(a.x, a.y));
            ua.y = h2u(__floats2half2_rn(a.z, a.w));
            ub.x = h2u(__floats2half2_rn(b.x, b.y));
            ub.y = h2u(__floats2half2_rn(b.z, b.w));
            *(uint2*)(s_keh + k * KROW + j) = ua;
            *(uint2*)(s_kvh + k * KROW + j) = ub;
        }
        s_q[t] = __half2float(g_Qh[(size_t)bn * 128 + t]);
    }
    __syncthreads();

    // K1/K2 mma (fp16 in, fp32 acc)
    float acc1[2][4][4], acc2[2][4][4];
#pragma unroll
    for (int m = 0; m < 2; ++m)
#pragma unroll
        for (int n = 0; n < 4; ++n)
#pragma unroll
            for (int c = 0; c < 4; ++c) { acc1[m][n][c] = 0.f; acc2[m][n][c] = 0.f; }

    const int arow = lane & 15, acol8 = (lane >> 4) * 8;
#pragma unroll
    for (int ks = 0; ks < 8; ++ks) {
        unsigned int a1[2][4], a2[2][4];
#pragma unroll
        for (int m = 0; m < 2; ++m) {
            ldsm_x4(a1[m], s_keh + (m * 16 + arow) * KROW + ks * 16 + acol8);
            ldsm_x4(a2[m], s_kvh + (m * 16 + arow) * KROW + ks * 16 + acol8);
        }
#pragma unroll
        for (int n = 0; n < 4; ++n) {
            int f = (((w * 4 + n) * 8 + ks) * 32) + lane;
            uint2 b1 = g_W1f[f];
            uint2 b2 = g_W2f[f];
            mma16816(acc1[0][n], a1[0], b1.x, b1.y);
            mma16816(acc1[1][n], a1[1], b1.x, b1.y);
            mma16816(acc2[0][n], a2[0], b2.x, b2.y);
            mma16816(acc2[1][n], a2[1], b2.x, b2.y);
        }
    }

    // logits[h=w][k] = (1/32) sum_i q*K1*K2
#pragma unroll
    for (int m = 0; m < 2; ++m) {
        float p0 = 0.f, p1 = 0.f;
#pragma unroll
        for (int n = 0; n < 4; ++n) {
            int j0 = w * 32 + n * 8 + tid4 * 2;
            float q0 = s_q[j0], q1 = s_q[j0 + 1];
            p0 += q0 * acc1[m][n][0] * acc2[m][n][0]
                + q1 * acc1[m][n][1] * acc2[m][n][1];
            p1 += q0 * acc1[m][n][2] * acc2[m][n][2]
                + q1 * acc1[m][n][3] * acc2[m][n][3];
        }
        p0 += __shfl_xor_sync(0xffffffffu, p0, 1);
        p0 += __shfl_xor_sync(0xffffffffu, p0, 2);
        p1 += __shfl_xor_sync(0xffffffffu, p1, 1);
        p1 += __shfl_xor_sync(0xffffffffu, p1, 2);
        if (tid4 == 0) {
            s_logits[w * 32 + m * 16 + g]     = p0 * (1.0f / 32.0f);
            s_logits[w * 32 + m * 16 + g + 8] = p1 * (1.0f / 32.0f);
        }
    }
    __syncwarp();

    // masked softmax: warp w = head, lane = neighbor k -> s_att
    {
        float l = s_logits[w * 32 + lane];
        l = (mk > 0.f) ? l : -3.402823466e38f;
        float mx = l;
#pragma unroll
        for (int off = 16; off > 0; off >>= 1)
            mx = fmaxf(mx, __shfl_xor_sync(0xffffffffu, mx, off));
        float e = expf(l - mx);
        float s = e;
#pragma unroll
        for (int off = 16; off > 0; off >>= 1)
            s += __shfl_xor_sync(0xffffffffu, s, off);
        s_att[w * 32 + lane] = mk * e / s;
    }

    cp_async_wait0();
    __syncthreads();

    // y[h][c] for ALL 4 heads; thread t owns cols [2t, 2t+2) -> each EV smem
    // element read exactly once per block.
    {
        float2 a0 = make_float2(0.f, 0.f), a1 = make_float2(0.f, 0.f);
        float2 a2 = make_float2(0.f, 0.f), a3 = make_float2(0.f, 0.f);
#pragma unroll 8
        for (int k = 0; k < 32; ++k) {
            float2 e  = *(const float2*)(s_ev + k * 256 + t * 2);
            float w0 = s_att[k];
            float w1 = s_att[32 + k];
            float w2 = s_att[64 + k];
            float w3 = s_att[96 + k];
            a0.x += w0 * e.x; a0.y += w0 * e.y;
            a1.x += w1 * e.x; a1.y += w1 * e.y;
            a2.x += w2 * e.x; a2.y += w2 * e.y;
            a3.x += w3 * e.x; a3.y += w3 * e.y;
        }
        __half* gy = g_Y + (size_t)bn * 1024 + t * 2;
        *(__half2*)(gy)       = __floats2half2_rn(a0.x, a0.y);
        *(__half2*)(gy + 256) = __floats2half2_rn(a1.x, a1.y);
        *(__half2*)(gy + 512) = __floats2half2_rn(a2.x, a2.y);
        *(__half2*)(gy + 768) = __floats2half2_rn(a3.x, a3.y);
    }
}

// ---------------- out: out = LN(h_V + Y @ Mfull) -----------------------------
// 125 blocks x 256 threads, 32 nodes/block. Warp w owns n-tiles {2w, 2w+1}
// over the FULL K=1024 (no split-K). Mfull streamed in 8 K-chunks (32 KB each)
// through a 3-buffer cp.async pipeline.
__global__ void __launch_bounds__(256)
out_kernel(const float* __restrict__ h_V,
           const float* __restrict__ mask_V,
           const float* __restrict__ gain,
           const float* __restrict__ bias,
           float* __restrict__ out) {
    extern __shared__ float smf[];
    float*  sRed = smf;                            // 32*132 = 4224 floats
    __half* sY   = (__half*)(sRed + 4224);         // 32*1032 halves
    uint2*  sMf  = (uint2*)(sY + 32 * 1032);       // 3 * 4096 uint2

    const int t    = threadIdx.x;
    const int w    = t >> 5;
    const int lane = t & 31;
    const int g    = lane >> 2;
    const int tid4 = lane & 3;
    const int node0 = blockIdx.x * 32;

    // group 0: Y tile (64 KB)
    {
#pragma unroll
        for (int it = 0; it < 16; ++it) {
            int f = it * 256 + t;              // 0..4095 (16B chunks)
            int r = f >> 7, c = f & 127;
            cp_async16(sY + r * 1032 + c * 8,
                       g_Y + (size_t)(node0 + r) * 1024 + c * 8);
        }
        cp_async_commit();
    }

    // Mf chunk issue: chunk c covers ks in [c*8, c*8+8) for all 16 nt tiles.
    auto issueMf = [&](int c) {
        uint2* dst = sMf + (c % 3) * 4096;
        const uint2* src = g_Mf;
#pragma unroll
        for (int it = 0; it < 8; ++it) {
            int i     = it * 256 + t;          // 0..2047 (16B units)
            int nt    = i >> 7;
            int inner = i & 127;
            cp_async16(dst + nt * 256 + inner * 2,
                       src + (nt * 64 + c * 8) * 32 + inner * 2);
        }
        cp_async_commit();
    };

    issueMf(0);
    issueMf(1);

    float acc[2][2][4];   // [nt_local][m][c]
#pragma unroll
    for (int nl = 0; nl < 2; ++nl)
#pragma unroll
        for (int m = 0; m < 2; ++m)
#pragma unroll
            for (int c = 0; c < 4; ++c) acc[nl][m][c] = 0.f;

    const int arow = lane & 15, acol8 = (lane >> 4) * 8;

    for (int c = 0; c < 8; ++c) {
        if (c + 2 < 8) issueMf(c + 2);
        int rem = 7 - c; if (rem > 2) rem = 2;
        if (rem == 2)      cp_async_wait2();
        else if (rem == 1) cp_async_wait1();
        else               cp_async_wait0();
        __syncthreads();

        const uint2* bbuf = sMf + (c % 3) * 4096;
#pragma unroll
        for (int ksl = 0; ksl < 8; ++ksl) {
            int ks = c * 8 + ksl;
            unsigned int a0[4], a1[4];
            ldsm_x4(a0, sY + arow * 1032 + ks * 16 + acol8);
            ldsm_x4(a1, sY + (16 + arow) * 1032 + ks * 16 + acol8);
#pragma unroll
            for (int nl = 0; nl < 2; ++nl) {
                uint2 b = bbuf[(w * 2 + nl) * 256 + ksl * 32 + lane];
                mma16816(acc[nl][0], a0, b.x, b.y);
                mma16816(acc[nl][1], a1, b.x, b.y);
            }
        }
        __syncthreads();   // protect buffer (c%3) before reuse at c+3
    }

    // C -> smem (full-K accumulators; no reduction pass)
#pragma unroll
    for (int nl = 0; nl < 2; ++nl) {
        int col = (w * 2 + nl) * 8 + tid4 * 2;
#pragma unroll
        for (int m = 0; m < 2; ++m) {
            int r0 = m * 16 + g;
            sRed[r0 * 132 + col]           = acc[nl][m][0];
            sRed[r0 * 132 + col + 1]       = acc[nl][m][1];
            sRed[(r0 + 8) * 132 + col]     = acc[nl][m][2];
            sRed[(r0 + 8) * 132 + col + 1] = acc[nl][m][3];
        }
    }
    __syncthreads();

    // epilogue: warp w handles rows w*4..w*4+3; lane owns one float4 per row
    {
        const float4* hv4 = (const float4*)h_V;
        const float4 gg = ((const float4*)gain)[lane];
        const float4 bb = ((const float4*)bias)[lane];
#pragma unroll
        for (int rr = 0; rr < 4; ++rr) {
            int r    = w * 4 + rr;
            int node = node0 + r;
            float4 cv = *(float4*)&sRed[r * 132 + lane * 4];
            float4 hv = hv4[(size_t)node * 32 + lane];
            float4 x;
            x.x = cv.x + hv.x;
            x.y = cv.y + hv.y;
            x.z = cv.z + hv.z;
            x.w = cv.w + hv.w;
            float sum = x.x + x.y + x.z + x.w;
            float sq  = x.x * x.x + x.y * x.y + x.z * x.z + x.w * x.w;
#pragma unroll
            for (int off = 16; off > 0; off >>= 1) {
                sum += __shfl_xor_sync(0xffffffffu, sum, off);
                sq  += __shfl_xor_sync(0xffffffffu, sq, off);
            }
            float mu  = sum * (1.f / 128.f);
            float var = (sq - sum * mu) * (1.f / 127.f);
            float sig = sqrtf(var + EPSC);
            float mk  = mask_V[node];
            float iv  = mk / (sig + EPSC);
            float4 o;
            o.x = (x.x - mu) * iv * gg.x + mk * bb.x;
            o.y = (x.y - mu) * iv * gg.y + mk * bb.y;
            o.z = (x.z - mu) * iv * gg.z + mk * bb.z;
            o.w = (x.w - mu) * iv * gg.w + mk * bb.w;
            ((float4*)out)[(size_t)node * 32 + lane] = o;
        }
    }
}

static const int ATTN_SMEM = (128 + 128 + 128 + 8192) * 4 + 2 * 32 * KROW * 2;
static const int OUT_SMEM  = 4224 * 4 + 32 * 1032 * 2 + 3 * 4096 * 8;

extern "C" void kernel_launch(void* const* d_in, const int* in_sizes, int n_in,
                              void* d_out, int out_size) {
    const float* h_V         = (const float*)d_in[0];
    const float* h_EV        = (const float*)d_in[1];
    const float* h_KV        = (const float*)d_in[2];
    const float* h_KE        = (const float*)d_in[3];
    const float* mask_V      = (const float*)d_in[4];
    const float* mask_attend = (const float*)d_in[5];
    const float* W_Q         = (const float*)d_in[6];
    const float* W_K1        = (const float*)d_in[7];
    const float* W_K2        = (const float*)d_in[8];
    const float* W_V         = (const float*)d_in[9];
    const float* W_O         = (const float*)d_in[10];
    const float* gain        = (const float*)d_in[11];
    const float* bias        = (const float*)d_in[12];
    float* out = (float*)d_out;

    pack_kernel<<<48, 256>>>(W_Q, W_K1, W_K2, W_V, W_O);
    qgemm_kernel<<<125, 128>>>(h_V);

    cudaFuncSetAttribute(attn_kernel,
                         cudaFuncAttributeMaxDynamicSharedMemorySize, ATTN_SMEM);
    attn_kernel<<<BB * NN, 128, ATTN_SMEM>>>(h_EV, h_KV, h_KE, mask_attend);

    cudaFuncSetAttribute(out_kernel,
                         cudaFuncAttributeMaxDynamicSharedMemorySize, OUT_SMEM);
    out_kernel<<<125, 256, OUT_SMEM>>>(h_V, mask_V, gain, bias, out);
}

// round 16
// speedup vs baseline: 1.3645x; 1.0472x over previous
#include <cuda_runtime.h>
#include <cuda_fp16.h>
#include <cstdint>
#include <math.h>

#define BB   2
#define NN   2000
#define KK   32
#define HH   128
#define EPSC 1e-6f

// ---------------- device scratch (__device__ globals, no alloc) -------------
__device__ uint2 g_WQf[16 * 8 * 32];
__device__ uint2 g_W1f[16 * 8 * 32];
__device__ uint2 g_W2f[16 * 8 * 32];
// Fused value matrix Mfull[1024 x 128] fp16 fragments (Mfull = W_V(head) x W_O)
__device__ uint2 g_Mf[16 * 64 * 32];
__device__ __half g_Qh[4000 * 128];
__device__ __half g_Y [4000 * 1024];

__device__ __forceinline__ unsigned int h2u(__half2 h) {
    return *(unsigned int*)&h;
}
__device__ __forceinline__ void cp_async16(void* dst_smem, const void* src) {
    unsigned int d = (unsigned int)__cvta_generic_to_shared(dst_smem);
    asm volatile("cp.async.cg.shared.global [%0], [%1], 16;" :: "r"(d), "l"(src));
}
__device__ __forceinline__ void cp_async_commit() {
    asm volatile("cp.async.commit_group;");
}
__device__ __forceinline__ void cp_async_wait0() {
    asm volatile("cp.async.wait_group 0;");
}
__device__ __forceinline__ void cp_async_wait1() {
    asm volatile("cp.async.wait_group 1;");
}

// ---------------- pack: weight fragments + Mfull ----------------------------
__global__ void pack_kernel(const float* __restrict__ WQ,
                            const float* __restrict__ WK1,
                            const float* __restrict__ WK2,
                            const float* __restrict__ WV,
                            const float* __restrict__ WO) {
    __shared__ float sWO[128 * 33];
    __shared__ float sWV[32 * 32];
    if (blockIdx.x < 16) {
        int t = blockIdx.x * 256 + threadIdx.x;   // 0..4095
        int lane = t & 31;
        int ks   = (t >> 5) & 7;
        int nt8  = t >> 8;
        int g    = lane >> 2;
        int tid4 = lane & 3;
        int n    = nt8 * 8 + g;
        int k0   = ks * 16 + tid4 * 2;
        uint2 uq, u1, u2;
        uq.x = h2u(__floats2half2_rn(WQ [n * 128 + k0],     WQ [n * 128 + k0 + 1]));
        uq.y = h2u(__floats2half2_rn(WQ [n * 128 + k0 + 8], WQ [n * 128 + k0 + 9]));
        u1.x = h2u(__floats2half2_rn(WK1[n * 128 + k0],     WK1[n * 128 + k0 + 1]));
        u1.y = h2u(__floats2half2_rn(WK1[n * 128 + k0 + 8], WK1[n * 128 + k0 + 9]));
        u2.x = h2u(__floats2half2_rn(WK2[n * 128 + k0],     WK2[n * 128 + k0 + 1]));
        u2.y = h2u(__floats2half2_rn(WK2[n * 128 + k0 + 8], WK2[n * 128 + k0 + 9]));
        g_WQf[t] = uq; g_W1f[t] = u1; g_W2f[t] = u2;
    } else {
        int bid = blockIdx.x - 16;        // 0..31
        int h   = bid >> 3;               // head
        int jc  = bid & 7;                // 32-wide j chunk within head
        int tid = threadIdx.x;
        for (int i = tid; i < 128 * 32; i += 256) {
            int o = i >> 5, ii = i & 31;
            sWO[o * 33 + ii] = WO[o * 128 + h * 32 + ii];
        }
        for (int i = tid; i < 32 * 32; i += 256) {
            int ii = i >> 5, jj = i & 31;
            sWV[ii * 32 + jj] = WV[(h * 32 + ii) * 256 + jc * 32 + jj];
        }
        __syncthreads();
        int o    = tid & 127;
        int jsel = tid >> 7;
        float wo[32];
#pragma unroll
        for (int ii = 0; ii < 32; ++ii) wo[ii] = sWO[o * 33 + ii];
        float m[16];
#pragma unroll
        for (int jj2 = 0; jj2 < 16; ++jj2) {
            int jj = jsel * 16 + jj2;
            float a = 0.f;
#pragma unroll
            for (int ii = 0; ii < 32; ++ii) a += sWV[ii * 32 + jj] * wo[ii];
            m[jj2] = a;
        }
        int ks = h * 16 + jc * 2 + jsel;
        int nt = o >> 3;
        int g  = o & 7;
#pragma unroll
        for (int tid4 = 0; tid4 < 4; ++tid4) {
            int k0l = tid4 * 2;
            uint2 u;
            u.x = h2u(__floats2half2_rn(m[k0l],     m[k0l + 1]));
            u.y = h2u(__floats2half2_rn(m[k0l + 8], m[k0l + 9]));
            g_Mf[(nt * 64 + ks) * 32 + (g << 2 | tid4)] = u;
        }
    }
}

// ---------------- PTX helpers ----------------
__device__ __forceinline__ void ldsm_x4(unsigned int* r, const void* p) {
    unsigned int a = (unsigned int)__cvta_generic_to_shared(p);
    asm volatile("ldmatrix.sync.aligned.m8n8.x4.shared.b16 {%0,%1,%2,%3}, [%4];"
                 : "=r"(r[0]), "=r"(r[1]), "=r"(r[2]), "=r"(r[3]) : "r"(a));
}
__device__ __forceinline__ void mma16816(float* d, const unsigned int* a,
                                         unsigned int b0, unsigned int b1) {
    asm volatile("mma.sync.aligned.m16n8k16.row.col.f32.f16.f16.f32 "
                 "{%0,%1,%2,%3}, {%4,%5,%6,%7}, {%8,%9}, {%0,%1,%2,%3};"
                 : "+f"(d[0]), "+f"(d[1]), "+f"(d[2]), "+f"(d[3])
                 : "r"(a[0]), "r"(a[1]), "r"(a[2]), "r"(a[3]), "r"(b0), "r"(b1));
}

// ---------------- qgemm: Q = h_V @ W_Q^T -> g_Qh (fp16 mma) -----------------
__global__ void __launch_bounds__(128)
qgemm_kernel(const float* __restrict__ h_V) {
    __shared__ __half sA[32 * 136];
    const int t    = threadIdx.x;
    const int w    = t >> 5;
    const int lane = t & 31;
    const int g    = lane >> 2;
    const int tid4 = lane & 3;
    const int node0 = blockIdx.x * 32;

    const float4* hv4 = (const float4*)h_V;
#pragma unroll
    for (int it = 0; it < 8; ++it) {
        int f4 = it * 128 + t;
        int r  = f4 >> 5, c4 = f4 & 31;
        float4 v = hv4[(size_t)(node0 + r) * 32 + c4];
        __half2* p = (__half2*)(sA + r * 136 + c4 * 4);
        p[0] = __floats2half2_rn(v.x, v.y);
        p[1] = __floats2half2_rn(v.z, v.w);
    }
    __syncthreads();

    float acc[2][4][4];
#pragma unroll
    for (int m = 0; m < 2; ++m)
#pragma unroll
        for (int n = 0; n < 4; ++n)
#pragma unroll
            for (int c = 0; c < 4; ++c) acc[m][n][c] = 0.f;

    const int arow = lane & 15, acol8 = (lane >> 4) * 8;
#pragma unroll
    for (int ks = 0; ks < 8; ++ks) {
        unsigned int a[2][4];
#pragma unroll
        for (int m = 0; m < 2; ++m)
            ldsm_x4(a[m], sA + (m * 16 + arow) * 136 + ks * 16 + acol8);
#pragma unroll
        for (int n = 0; n < 4; ++n) {
            uint2 b = g_WQf[(((w * 4 + n) * 8 + ks) * 32) + lane];
            mma16816(acc[0][n], a[0], b.x, b.y);
            mma16816(acc[1][n], a[1], b.x, b.y);
        }
    }
#pragma unroll
    for (int m = 0; m < 2; ++m)
#pragma unroll
        for (int n = 0; n < 4; ++n) {
            int col = w * 32 + n * 8 + tid4 * 2;
            int r0  = node0 + m * 16 + g;
            *(__half2*)&g_Qh[(size_t)r0 * 128 + col] =
                __floats2half2_rn(acc[m][n][0], acc[m][n][1]);
            *(__half2*)&g_Qh[(size_t)(r0 + 8) * 128 + col] =
                __floats2half2_rn(acc[m][n][2], acc[m][n][3]);
        }
}

// ---------------- attn: per node -> Y (EV staged as fp16) -------------------
#define KROW 136
__global__ void __launch_bounds__(128, 4)
attn_kernel(const float* __restrict__ h_EV,
            const float* __restrict__ h_KV,
            const float* __restrict__ h_KE,
            const float* __restrict__ mask_attend) {
    extern __shared__ float smbuf[];
    float*  s_q      = smbuf;                    // 128
    float*  s_logits = s_q + 128;                // 128
    float*  s_att    = s_logits + 128;           // 128
    __half* s_evh    = (__half*)(s_att + 128);   // 32*256 halves (16 KB)
    __half* s_keh    = s_evh + 32 * 256;         // 32*KROW
    __half* s_kvh    = s_keh + 32 * KROW;        // 32*KROW

    const int bn   = blockIdx.x;
    const int t    = threadIdx.x;
    const int w    = t >> 5;
    const int lane = t & 31;
    const int g    = lane >> 2;
    const int tid4 = lane & 3;

    const float mk = mask_attend[(size_t)bn * KK + lane];

    // stage EV as fp16 (halves smem crossbar traffic vs fp32)
    {
        const float4* gev = (const float4*)(h_EV + (size_t)bn * KK * 256);
#pragma unroll
        for (int it = 0; it < 16; ++it) {
            int idx = it * 128 + t;              // float4 index, row = idx>>6
            float4 e = gev[idx];
            uint2 u;
            u.x = h2u(__floats2half2_rn(e.x, e.y));
            u.y = h2u(__floats2half2_rn(e.z, e.w));
            *(uint2*)(s_evh + (idx >> 6) * 256 + (idx & 63) * 4) = u;
        }
    }

    // stage KE/KV as fp16
    {
        const float4* gke = (const float4*)(h_KE + (size_t)bn * KK * 128);
        const float4* gkv = (const float4*)(h_KV + (size_t)bn * KK * 128);
#pragma unroll
        for (int r = 0; r < 8; ++r) {
            int e4 = r * 128 + t;
            int k  = e4 >> 5;
            int j  = (e4 & 31) * 4;
            float4 a = gke[e4];
            float4 b = gkv[e4];
            uint2 ua, ub;
            ua.x = h2u(__floats2half2_rn(a.x, a.y));
            ua.y = h2u(__floats2half2_rn(a.z, a.w));
            ub.x = h2u(__floats2half2_rn(b.x, b.y));
            ub.y = h2u(__floats2half2_rn(b.z, b.w));
            *(uint2*)(s_keh + k * KROW + j) = ua;
            *(uint2*)(s_kvh + k * KROW + j) = ub;
        }
        s_q[t] = __half2float(g_Qh[(size_t)bn * 128 + t]);
    }
    __syncthreads();

    // K1/K2 mma (fp16 in, fp32 acc)
    float acc1[2][4][4], acc2[2][4][4];
#pragma unroll
    for (int m = 0; m < 2; ++m)
#pragma unroll
        for (int n = 0; n < 4; ++n)
#pragma unroll
            for (int c = 0; c < 4; ++c) { acc1[m][n][c] = 0.f; acc2[m][n][c] = 0.f; }

    const int arow = lane & 15, acol8 = (lane >> 4) * 8;
#pragma unroll
    for (int ks = 0; ks < 8; ++ks) {
        unsigned int a1[2][4], a2[2][4];
#pragma unroll
        for (int m = 0; m < 2; ++m) {
            ldsm_x4(a1[m], s_keh + (m * 16 + arow) * KROW + ks * 16 + acol8);
            ldsm_x4(a2[m], s_kvh + (m * 16 + arow) * KROW + ks * 16 + acol8);
        }
#pragma unroll
        for (int n = 0; n < 4; ++n) {
            int f = (((w * 4 + n) * 8 + ks) * 32) + lane;
            uint2 b1 = g_W1f[f];
            uint2 b2 = g_W2f[f];
            mma16816(acc1[0][n], a1[0], b1.x, b1.y);
            mma16816(acc1[1][n], a1[1], b1.x, b1.y);
            mma16816(acc2[0][n], a2[0], b2.x, b2.y);
            mma16816(acc2[1][n], a2[1], b2.x, b2.y);
        }
    }

    // logits[h=w][k] = (1/32) sum_i q*K1*K2
#pragma unroll
    for (int m = 0; m < 2; ++m) {
        float p0 = 0.f, p1 = 0.f;
#pragma unroll
        for (int n = 0; n < 4; ++n) {
            int j0 = w * 32 + n * 8 + tid4 * 2;
            float q0 = s_q[j0], q1 = s_q[j0 + 1];
            p0 += q0 * acc1[m][n][0] * acc2[m][n][0]
                + q1 * acc1[m][n][1] * acc2[m][n][1];
            p1 += q0 * acc1[m][n][2] * acc2[m][n][2]
                + q1 * acc1[m][n][3] * acc2[m][n][3];
        }
        p0 += __shfl_xor_sync(0xffffffffu, p0, 1);
        p0 += __shfl_xor_sync(0xffffffffu, p0, 2);
        p1 += __shfl_xor_sync(0xffffffffu, p1, 1);
        p1 += __shfl_xor_sync(0xffffffffu, p1, 2);
        if (tid4 == 0) {
            s_logits[w * 32 + m * 16 + g]     = p0 * (1.0f / 32.0f);
            s_logits[w * 32 + m * 16 + g + 8] = p1 * (1.0f / 32.0f);
        }
    }
    __syncwarp();

    // masked softmax: warp w = head, lane = neighbor k -> s_att
    {
        float l = s_logits[w * 32 + lane];
        l = (mk > 0.f) ? l : -3.402823466e38f;
        float mx = l;
#pragma unroll
        for (int off = 16; off > 0; off >>= 1)
            mx = fmaxf(mx, __shfl_xor_sync(0xffffffffu, mx, off));
        float e = expf(l - mx);
        float s = e;
#pragma unroll
        for (int off = 16; off > 0; off >>= 1)
            s += __shfl_xor_sync(0xffffffffu, s, off);
        s_att[w * 32 + lane] = mk * e / s;
    }
    __syncthreads();

    // y[h][c] for ALL 4 heads; thread t owns cols [2t, 2t+2); EV read once.
    {
        float2 a0 = make_float2(0.f, 0.f), a1 = make_float2(0.f, 0.f);
        float2 a2 = make_float2(0.f, 0.f), a3 = make_float2(0.f, 0.f);
#pragma unroll 8
        for (int k = 0; k < 32; ++k) {
            __half2 eh = *(const __half2*)(s_evh + k * 256 + t * 2);
            float2 e = __half22float2(eh);
            float w0 = s_att[k];
            float w1 = s_att[32 + k];
            float w2 = s_att[64 + k];
            float w3 = s_att[96 + k];
            a0.x += w0 * e.x; a0.y += w0 * e.y;
            a1.x += w1 * e.x; a1.y += w1 * e.y;
            a2.x += w2 * e.x; a2.y += w2 * e.y;
            a3.x += w3 * e.x; a3.y += w3 * e.y;
        }
        __half* gy = g_Y + (size_t)bn * 1024 + t * 2;
        *(__half2*)(gy)       = __floats2half2_rn(a0.x, a0.y);
        *(__half2*)(gy + 256) = __floats2half2_rn(a1.x, a1.y);
        *(__half2*)(gy + 512) = __floats2half2_rn(a2.x, a2.y);
        *(__half2*)(gy + 768) = __floats2half2_rn(a3.x, a3.y);
    }
}

// ---------------- out: out = LN(h_V + Y @ Mfull) -----------------------------
// 250 blocks x 256 threads, 16 nodes/block (2 blocks/SM). Warp w owns n-tiles
// {2w, 2w+1} over full K=1024. Mfull streamed in 8 K-chunks, 2-buffer pipeline.
__global__ void __launch_bounds__(256)
out_kernel(const float* __restrict__ h_V,
           const float* __restrict__ mask_V,
           const float* __restrict__ gain,
           const float* __restrict__ bias,
           float* __restrict__ out) {
    extern __shared__ float smf[];
    float*  sRed = smf;                            // 16*132 floats
    __half* sY   = (__half*)(sRed + 16 * 132);     // 16*1032 halves
    uint2*  sMf  = (uint2*)(sY + 16 * 1032);       // 2 * 4096 uint2

    const int t    = threadIdx.x;
    const int w    = t >> 5;
    const int lane = t & 31;
    const int g    = lane >> 2;
    const int tid4 = lane & 3;
    const int node0 = blockIdx.x * 16;

    // group: Y tile (32 KB)
    {
#pragma unroll
        for (int it = 0; it < 8; ++it) {
            int f = it * 256 + t;              // 0..2047 (16B chunks)
            int r = f >> 7, c = f & 127;
            cp_async16(sY + r * 1032 + c * 8,
                       g_Y + (size_t)(node0 + r) * 1024 + c * 8);
        }
        cp_async_commit();
    }

    // Mf chunk issue: chunk c covers ks in [c*8, c*8+8) for all 16 nt tiles.
    auto issueMf = [&](int c) {
        uint2* dst = sMf + (c & 1) * 4096;
        const uint2* src = g_Mf;
#pragma unroll
        for (int it = 0; it < 8; ++it) {
            int i     = it * 256 + t;          // 0..2047 (16B units)
            int nt    = i >> 7;
            int inner = i & 127;
            cp_async16(dst + nt * 256 + inner * 2,
                       src + (nt * 64 + c * 8) * 32 + inner * 2);
        }
        cp_async_commit();
    };

    issueMf(0);

    float acc[2][4];      // [nt_local][c]
#pragma unroll
    for (int nl = 0; nl < 2; ++nl)
#pragma unroll
        for (int c = 0; c < 4; ++c) acc[nl][c] = 0.f;

    const int arow = lane & 15, acol8 = (lane >> 4) * 8;

    for (int c = 0; c < 8; ++c) {
        if (c + 1 < 8) issueMf(c + 1);
        if (c + 1 < 8) cp_async_wait1();   // Y + Mf(c) complete
        else           cp_async_wait0();
        __syncthreads();

        const uint2* bbuf = sMf + (c & 1) * 4096;
#pragma unroll
        for (int ksl = 0; ksl < 8; ++ksl) {
            int ks = c * 8 + ksl;
            unsigned int a0[4];
            ldsm_x4(a0, sY + arow * 1032 + ks * 16 + acol8);
#pragma unroll
            for (int nl = 0; nl < 2; ++nl) {
                uint2 b = bbuf[(w * 2 + nl) * 256 + ksl * 32 + lane];
                mma16816(acc[nl], a0, b.x, b.y);
            }
        }
        __syncthreads();   // buffer (c&1) safe to overwrite at c+2
    }

    // C -> smem (rows g, g+8; cols per n-tile)
#pragma unroll
    for (int nl = 0; nl < 2; ++nl) {
        int col = (w * 2 + nl) * 8 + tid4 * 2;
        sRed[g * 132 + col]           = acc[nl][0];
        sRed[g * 132 + col + 1]       = acc[nl][1];
        sRed[(g + 8) * 132 + col]     = acc[nl][2];
        sRed[(g + 8) * 132 + col + 1] = acc[nl][3];
    }
    __syncthreads();

    // epilogue: warp w handles rows 2w, 2w+1; lane owns one float4 per row
    {
        const float4* hv4 = (const float4*)h_V;
        const float4 gg = ((const float4*)gain)[lane];
        const float4 bb = ((const float4*)bias)[lane];
#pragma unroll
        for (int rr = 0; rr < 2; ++rr) {
            int r    = w * 2 + rr;
            int node = node0 + r;
            float4 cv = *(float4*)&sRed[r * 132 + lane * 4];
            float4 hv = hv4[(size_t)node * 32 + lane];
            float4 x;
            x.x = cv.x + hv.x;
            x.y = cv.y + hv.y;
            x.z = cv.z + hv.z;
            x.w = cv.w + hv.w;
            float sum = x.x + x.y + x.z + x.w;
            float sq  = x.x * x.x + x.y * x.y + x.z * x.z + x.w * x.w;
#pragma unroll
            for (int off = 16; off > 0; off >>= 1) {
                sum += __shfl_xor_sync(0xffffffffu, sum, off);
                sq  += __shfl_xor_sync(0xffffffffu, sq, off);
            }
            float mu  = sum * (1.f / 128.f);
            float var = (sq - sum * mu) * (1.f / 127.f);
            float sig = sqrtf(var + EPSC);
            float mk  = mask_V[node];
            float iv  = mk / (sig + EPSC);
            float4 o;
            o.x = (x.x - mu) * iv * gg.x + mk * bb.x;
            o.y = (x.y - mu) * iv * gg.y + mk * bb.y;
            o.z = (x.z - mu) * iv * gg.z + mk * bb.z;
            o.w = (x.w - mu) * iv * gg.w + mk * bb.w;
            ((float4*)out)[(size_t)node * 32 + lane] = o;
        }
    }
}

static const int ATTN_SMEM = (128 * 3) * 4 + 32 * 256 * 2 + 2 * 32 * KROW * 2;
static const int OUT_SMEM  = 16 * 132 * 4 + 16 * 1032 * 2 + 2 * 4096 * 8;

extern "C" void kernel_launch(void* const* d_in, const int* in_sizes, int n_in,
                              void* d_out, int out_size) {
    const float* h_V         = (const float*)d_in[0];
    const float* h_EV        = (const float*)d_in[1];
    const float* h_KV        = (const float*)d_in[2];
    const float* h_KE        = (const float*)d_in[3];
    const float* mask_V      = (const float*)d_in[4];
    const float* mask_attend = (const float*)d_in[5];
    const float* W_Q         = (const float*)d_in[6];
    const float* W_K1        = (const float*)d_in[7];
    const float* W_K2        = (const float*)d_in[8];
    const float* W_V         = (const float*)d_in[9];
    const float* W_O         = (const float*)d_in[10];
    const float* gain        = (const float*)d_in[11];
    const float* bias        = (const float*)d_in[12];
    float* out = (float*)d_out;

    pack_kernel<<<48, 256>>>(W_Q, W_K1, W_K2, W_V, W_O);
    qgemm_kernel<<<125, 128>>>(h_V);

    cudaFuncSetAttribute(attn_kernel,
                         cudaFuncAttributeMaxDynamicSharedMemorySize, ATTN_SMEM);
    attn_kernel<<<BB * NN, 128, ATTN_SMEM>>>(h_EV, h_KV, h_KE, mask_attend);

    cudaFuncSetAttribute(out_kernel,
                         cudaFuncAttributeMaxDynamicSharedMemorySize, OUT_SMEM);
    out_kernel<<<250, 256, OUT_SMEM>>>(h_V, mask_V, gain, bias, out);
}